// round 16
// baseline (speedup 1.0000x reference)
#include <cuda_runtime.h>
#include <cstdint>

// Problem constants (fixed shapes)
constexpr int B  = 16;
constexpr int N  = 4096;
constexpr int K  = 32;
constexpr int BN = B * N;   // 65536

// compose kernel geometry (round-13 proven layout + smem stash)
constexpr int TSR = 296;                  // rot tile stride (floats), %32==8 -> conflict-free
constexpr int TST = 104;                  // trans tile stride (floats), %32==8
constexpr int WSM = 4 * TSR + 4 * TST;    // 1600 floats per warp staging
constexpr int STASH_FLOATS = 32 * 13;     // 416 floats per warp (13 sums x 32 bn)
constexpr int WARP_FLOATS  = WSM + STASH_FLOATS;  // 2016
constexpr int CWARPS   = 16;
constexpr int CTHREADS = CWARPS * 32;     // 512
constexpr int NCHUNK   = BN / 32;         // 2048 chunks of 32 bn
constexpr int CSMEM    = CWARPS * WARP_FLOATS * 4; // 129024 B

// packed frames: 64B-aligned rows, floats [rot 9 | trans 3 | pad 4].
__device__ float g_frames[BN * 16];

// ---------------------------------------------------------------------------
// Kernel 1: repack frames into 64-byte rows (round-13 proven version).
// ---------------------------------------------------------------------------
__global__ __launch_bounds__(256) void repack_frames_kernel(
    const float* __restrict__ fr, const float* __restrict__ ft) {
    __shared__ __align__(16) float s[256 * 12];
    int t = threadIdx.x;
    int blk = blockIdx.x;

    const float4* fr4 = (const float4*)fr + (size_t)blk * 576;
#pragma unroll
    for (int q = 0; q < 2; q++) {
        float4 v = fr4[q * 256 + t];
        int e = (q * 256 + t) * 4;
#pragma unroll
        for (int u = 0; u < 4; u++) {
            int el = e + u;
            int fi = el / 9, c = el - fi * 9;
            s[fi * 12 + c] = (&v.x)[u];
        }
    }
    if (t < 64) {
        float4 v = fr4[512 + t];
        int e = (512 + t) * 4;
#pragma unroll
        for (int u = 0; u < 4; u++) {
            int el = e + u;
            int fi = el / 9, c = el - fi * 9;
            s[fi * 12 + c] = (&v.x)[u];
        }
    }
    const float4* ft4 = (const float4*)ft + (size_t)blk * 192;
    if (t < 192) {
        float4 v = ft4[t];
        int e = t * 4;
#pragma unroll
        for (int u = 0; u < 4; u++) {
            int el = e + u;
            int fi = el / 3, c = el - fi * 3;
            s[fi * 12 + 9 + c] = (&v.x)[u];
        }
    }
    __syncthreads();

    const float4* row = (const float4*)(s + t * 12);
    float4* o = (float4*)g_frames + ((size_t)blk * 256 + t) * 4;  // 64B rows
    o[0] = row[0]; o[1] = row[1]; o[2] = row[2];
}

// ---------------------------------------------------------------------------
// SO(3) projection (Jacobi eigendecomposition of A^T A), per-thread.
// ---------------------------------------------------------------------------
template <int p, int q, int r>
__device__ __forceinline__ void jrot(float S[3][3], float V[3][3]) {
    float spq = S[p][q];
    if (fabsf(spq) > 1e-30f) {
        float tau = (S[q][q] - S[p][p]) / (2.0f * spq);
        float t   = copysignf(1.0f, tau) / (fabsf(tau) + sqrtf(1.0f + tau * tau));
        float c   = rsqrtf(1.0f + t * t);
        float sn  = t * c;
        float spp = S[p][p], sqq = S[q][q];
        S[p][p] = spp - t * spq;
        S[q][q] = sqq + t * spq;
        S[p][q] = 0.0f; S[q][p] = 0.0f;
        float srp = S[r][p], srq = S[r][q];
        S[r][p] = c * srp - sn * srq; S[p][r] = S[r][p];
        S[r][q] = sn * srp + c * srq; S[q][r] = S[r][q];
#pragma unroll
        for (int i = 0; i < 3; i++) {
            float vip = V[i][p], viq = V[i][q];
            V[i][p] = c * vip - sn * viq;
            V[i][q] = sn * vip + c * viq;
        }
    }
}

__device__ __forceinline__ void svd_project_write(const float* stash, float4* o) {
    float a[3][3] = {{stash[0], stash[1], stash[2]},
                     {stash[3], stash[4], stash[5]},
                     {stash[6], stash[7], stash[8]}};
    float inv = __fdividef(1.0f, stash[12]);
    float t0 = stash[9] * inv, t1 = stash[10] * inv, t2 = stash[11] * inv;

    float S[3][3];
#pragma unroll
    for (int c = 0; c < 3; c++)
#pragma unroll
        for (int d = c; d < 3; d++) {
            float v = a[0][c] * a[0][d] + a[1][c] * a[1][d] + a[2][c] * a[2][d];
            S[c][d] = v; S[d][c] = v;
        }

    float V[3][3] = {{1, 0, 0}, {0, 1, 0}, {0, 0, 1}};
#pragma unroll
    for (int sweep = 0; sweep < 5; sweep++) {
        jrot<0, 1, 2>(S, V);
        jrot<0, 2, 1>(S, V);
        jrot<1, 2, 0>(S, V);
    }

    float l0 = S[0][0], l1 = S[1][1], l2 = S[2][2];
    float v0x = V[0][0], v0y = V[1][0], v0z = V[2][0];
    float v1x = V[0][1], v1y = V[1][1], v1z = V[2][1];
    float v2x = V[0][2], v2y = V[1][2], v2z = V[2][2];

#define CSWAP(la, lb, ax, ay, az, bx, by, bz)                                  \
    if (la < lb) {                                                             \
        float tmp;                                                             \
        tmp = la; la = lb; lb = tmp;                                           \
        tmp = ax; ax = bx; bx = tmp;                                           \
        tmp = ay; ay = by; by = tmp;                                           \
        tmp = az; az = bz; bz = tmp;                                           \
    }
    CSWAP(l0, l1, v0x, v0y, v0z, v1x, v1y, v1z)
    CSWAP(l0, l2, v0x, v0y, v0z, v2x, v2y, v2z)
    CSWAP(l1, l2, v1x, v1y, v1z, v2x, v2y, v2z)
#undef CSWAP

    float cx = v1y * v2z - v1z * v2y;
    float cy = v1z * v2x - v1x * v2z;
    float cz = v1x * v2y - v1y * v2x;
    float det = v0x * cx + v0y * cy + v0z * cz;
    if (det < 0.0f) { v2x = -v2x; v2y = -v2y; v2z = -v2z; }

    float u0x = a[0][0] * v0x + a[0][1] * v0y + a[0][2] * v0z;
    float u0y = a[1][0] * v0x + a[1][1] * v0y + a[1][2] * v0z;
    float u0z = a[2][0] * v0x + a[2][1] * v0y + a[2][2] * v0z;
    float inv0 = rsqrtf(u0x * u0x + u0y * u0y + u0z * u0z + 1e-30f);
    u0x *= inv0; u0y *= inv0; u0z *= inv0;

    float u1x = a[0][0] * v1x + a[0][1] * v1y + a[0][2] * v1z;
    float u1y = a[1][0] * v1x + a[1][1] * v1y + a[1][2] * v1z;
    float u1z = a[2][0] * v1x + a[2][1] * v1y + a[2][2] * v1z;
    float dp = u0x * u1x + u0y * u1y + u0z * u1z;
    u1x -= dp * u0x; u1y -= dp * u0y; u1z -= dp * u0z;
    float inv1 = rsqrtf(u1x * u1x + u1y * u1y + u1z * u1z + 1e-30f);
    u1x *= inv1; u1y *= inv1; u1z *= inv1;

    float u2x = u0y * u1z - u0z * u1y;
    float u2y = u0z * u1x - u0x * u1z;
    float u2z = u0x * u1y - u0y * u1x;

    float R00 = u0x * v0x + u1x * v1x + u2x * v2x;
    float R01 = u0x * v0y + u1x * v1y + u2x * v2y;
    float R02 = u0x * v0z + u1x * v1z + u2x * v2z;
    float R10 = u0y * v0x + u1y * v1x + u2y * v2x;
    float R11 = u0y * v0y + u1y * v1y + u2y * v2y;
    float R12 = u0y * v0z + u1y * v1z + u2y * v2z;
    float R20 = u0z * v0x + u1z * v1x + u2z * v2x;
    float R21 = u0z * v0y + u1z * v1y + u2z * v2y;
    float R22 = u0z * v0z + u1z * v1z + u2z * v2z;

    o[0] = make_float4(R00, R01, R02, R10);
    o[1] = make_float4(R11, R12, R20, R21);
    o[2] = make_float4(R22, t0, t1, t2);
}

// ---------------------------------------------------------------------------
// Kernel 2 (compose + average + SVD) — round-13 structure with the register
// stash replaced by a per-warp smem stash: after the butterfly, lane s==0 of
// each group writes its 13 sums (4 lanes x 13 STS, stride-13 -> no conflicts);
// the epilogue reads each lane's 13 values back (stride-13 scalar LDS,
// gcd(13,32)=1 -> conflict-free). Removes 13 SHFL/iter and frees 13
// long-lived registers in a kernel previously at the 128-reg ceiling.
// ---------------------------------------------------------------------------
__global__ __launch_bounds__(CTHREADS) void compose_svd_kernel(
    const float* __restrict__ pair_rot,
    const float* __restrict__ pair_trans,
    const float* __restrict__ conf,
    const int*   __restrict__ topo,
    float*       __restrict__ out) {

    extern __shared__ float sm[];
    int tid  = threadIdx.x;
    int warp = tid >> 5;
    int lane = tid & 31;
    int g    = lane >> 3;
    int s    = lane & 7;

    int chunk = blockIdx.x + 148 * warp;   // balanced: every SM ~13-14 chunks
    if (chunk >= NCHUNK) return;           // uniform per warp; no __syncthreads

    int b = chunk >> 7;                    // 128 chunks per batch
    const float4* tab4 = (const float4*)g_frames + (size_t)(b << 12) * 4;

    float* rotbuf   = sm + warp * WARP_FLOATS;
    float* trnbuf   = rotbuf + 4 * TSR;
    float* stashbuf = rotbuf + WSM;        // 32 bn x 13 sums
    float4* rb4 = (float4*)rotbuf;         // tile stride 74 float4
    float4* tb4 = (float4*)trnbuf;         // tile stride 26 float4

    const float4* pr4 = (const float4*)pair_rot;
    const float4* pt4 = (const float4*)pair_trans;

    size_t chunkbn = (size_t)chunk * 32;

    // --- prologue: topo + conf for iteration 0 ---
    int   jj[4];
    float wgt[4];
    {
        const int*   tpb = topo + (chunkbn + g) * K;
        const float* cfb = conf + (chunkbn + g) * K;
#pragma unroll
        for (int i = 0; i < 4; i++) {
            jj[i]  = tpb[s + 8 * i];
            wgt[i] = cfb[s + 8 * i];
        }
    }

    for (int it = 0; it < 8; it++) {
        size_t bn0 = chunkbn + it * 4;

        // --- random frame gathers FIRST (indices already resident) ---
        float4 F[4][3];
#pragma unroll
        for (int i = 0; i < 4; i++) {
            const float4* Fp = tab4 + (size_t)jj[i] * 4;
            F[i][0] = Fp[0]; F[i][1] = Fp[1]; F[i][2] = Fp[2];
        }

        // --- stage pair tiles (coalesced float4 loads, padded smem) ---
#pragma unroll
        for (int q = 0; q < 9; q++) {
            int f = q * 32 + lane;             // 0..287
            int t = f / 72, w = f - t * 72;
            rb4[t * 74 + w] = pr4[bn0 * 72 + f];
        }
#pragma unroll
        for (int q = 0; q < 3; q++) {
            int f = q * 32 + lane;             // 0..95
            int t = f / 24, w = f - t * 24;
            tb4[t * 26 + w] = pt4[bn0 * 24 + f];
        }

        // --- prefetch NEXT iteration's topo + conf (full-iteration slack) ---
        int   jjn[4];
        float wgtn[4];
        if (it < 7) {
            const int*   tpbn = topo + (bn0 + 4 + g) * K;
            const float* cfbn = conf + (bn0 + 4 + g) * K;
#pragma unroll
            for (int i = 0; i < 4; i++) {
                jjn[i]  = tpbn[s + 8 * i];
                wgtn[i] = cfbn[s + 8 * i];
            }
        }
        __syncwarp();

        float acc[13];
#pragma unroll
        for (int v = 0; v < 13; v++) acc[v] = 0.0f;

#pragma unroll
        for (int i = 0; i < 4; i++) {
            int k = s + 8 * i;
            const float* P = rotbuf + g * TSR + k * 9;   // conflict-free LDS
            const float* Q = trnbuf + g * TST + k * 3;

            float w = wgt[i];
            float R0x = F[i][0].x, R0y = F[i][0].y, R0z = F[i][0].z;
            float R1x = F[i][0].w, R1y = F[i][1].x, R1z = F[i][1].y;
            float R2x = F[i][1].z, R2y = F[i][1].w, R2z = F[i][2].x;
            float tx  = F[i][2].y, ty  = F[i][2].z, tz  = F[i][2].w;

#pragma unroll
            for (int c = 0; c < 3; c++) {
                float p0 = P[c], p1 = P[3 + c], p2 = P[6 + c];
                acc[0 + c] += w * (R0x * p0 + R0y * p1 + R0z * p2);
                acc[3 + c] += w * (R1x * p0 + R1y * p1 + R1z * p2);
                acc[6 + c] += w * (R2x * p0 + R2y * p1 + R2z * p2);
            }
            float q0 = Q[0], q1 = Q[1], q2 = Q[2];
            acc[9]  += w * (R0x * q0 + R0y * q1 + R0z * q2 + tx);
            acc[10] += w * (R1x * q0 + R1y * q1 + R1z * q2 + ty);
            acc[11] += w * (R2x * q0 + R2y * q1 + R2z * q2 + tz);
            acc[12] += w;
        }
        __syncwarp();   // staging buffer reused next iteration

        // --- butterfly reduce within 8-lane groups ---
#pragma unroll
        for (int v = 0; v < 13; v++) {
            acc[v] += __shfl_xor_sync(0xffffffffu, acc[v], 4);
            acc[v] += __shfl_xor_sync(0xffffffffu, acc[v], 2);
            acc[v] += __shfl_xor_sync(0xffffffffu, acc[v], 1);
        }

        // --- stash to smem: lane s==0 of each group writes its 13 sums ---
        if (s == 0) {
            float* dst = stashbuf + (it * 4 + g) * 13;
#pragma unroll
            for (int v = 0; v < 13; v++) dst[v] = acc[v];
        }

        // --- rotate prefetched registers ---
        if (it < 7) {
#pragma unroll
            for (int i = 0; i < 4; i++) {
                jj[i]  = jjn[i];
                wgt[i] = wgtn[i];
            }
        }
    }
    __syncwarp();   // all stash writes visible to all lanes

    // --- epilogue: 32 fully-parallel SVDs, one bn per lane ---
    float st[13];
    const float* srcp = stashbuf + lane * 13;   // stride 13: conflict-free
#pragma unroll
    for (int v = 0; v < 13; v++) st[v] = srcp[v];

    float4* o = (float4*)out + (chunkbn + lane) * 3;
    svd_project_write(st, o);
}

// ---------------------------------------------------------------------------
extern "C" void kernel_launch(void* const* d_in, const int* in_sizes, int n_in,
                              void* d_out, int out_size) {
    const float* frames_rot   = (const float*)d_in[0];
    const float* frames_trans = (const float*)d_in[1];
    const float* pair_rot     = (const float*)d_in[2];
    const float* pair_trans   = (const float*)d_in[3];
    const float* confidences  = (const float*)d_in[4];
    const int*   topology     = (const int*)d_in[5];
    float*       out          = (float*)d_out;

    cudaFuncSetAttribute(compose_svd_kernel,
                         cudaFuncAttributeMaxDynamicSharedMemorySize, CSMEM);

    repack_frames_kernel<<<BN / 256, 256>>>(frames_rot, frames_trans);
    compose_svd_kernel<<<148, CTHREADS, CSMEM>>>(pair_rot, pair_trans,
                                                 confidences, topology, out);
}

// round 17
// speedup vs baseline: 1.0743x; 1.0743x over previous
#include <cuda_runtime.h>
#include <cstdint>

// Problem constants (fixed shapes)
constexpr int B  = 16;
constexpr int N  = 4096;
constexpr int K  = 32;
constexpr int BN = B * N;   // 65536

// compose kernel geometry (round-13 proven layout)
constexpr int TSR = 296;                  // rot tile stride (floats), %32==8 -> conflict-free
constexpr int TST = 104;                  // trans tile stride (floats), %32==8
constexpr int WSM = 4 * TSR + 4 * TST;    // 1600 floats per warp staging
constexpr int CWARPS   = 16;
constexpr int CTHREADS = CWARPS * 32;     // 512
constexpr int NCHUNK   = BN / 32;         // 2048 chunks of 32 bn
constexpr int CSMEM    = CWARPS * WSM * 4; // 102400 B

// packed frames: 64B-aligned rows, floats [rot 9 | trans 3 | pad 4].
__device__ float g_frames[BN * 16];

// ---------------------------------------------------------------------------
// Kernel 1: repack frames into 64-byte rows (round-13 proven version).
// ---------------------------------------------------------------------------
__global__ __launch_bounds__(256) void repack_frames_kernel(
    const float* __restrict__ fr, const float* __restrict__ ft) {
    __shared__ __align__(16) float s[256 * 12];
    int t = threadIdx.x;
    int blk = blockIdx.x;

    const float4* fr4 = (const float4*)fr + (size_t)blk * 576;
#pragma unroll
    for (int q = 0; q < 2; q++) {
        float4 v = fr4[q * 256 + t];
        int e = (q * 256 + t) * 4;
#pragma unroll
        for (int u = 0; u < 4; u++) {
            int el = e + u;
            int fi = el / 9, c = el - fi * 9;
            s[fi * 12 + c] = (&v.x)[u];
        }
    }
    if (t < 64) {
        float4 v = fr4[512 + t];
        int e = (512 + t) * 4;
#pragma unroll
        for (int u = 0; u < 4; u++) {
            int el = e + u;
            int fi = el / 9, c = el - fi * 9;
            s[fi * 12 + c] = (&v.x)[u];
        }
    }
    const float4* ft4 = (const float4*)ft + (size_t)blk * 192;
    if (t < 192) {
        float4 v = ft4[t];
        int e = t * 4;
#pragma unroll
        for (int u = 0; u < 4; u++) {
            int el = e + u;
            int fi = el / 3, c = el - fi * 3;
            s[fi * 12 + 9 + c] = (&v.x)[u];
        }
    }
    __syncthreads();

    const float4* row = (const float4*)(s + t * 12);
    float4* o = (float4*)g_frames + ((size_t)blk * 256 + t) * 4;  // 64B rows
    o[0] = row[0]; o[1] = row[1]; o[2] = row[2];
}

// ---------------------------------------------------------------------------
// SO(3) projection (Jacobi eigendecomposition of A^T A), per-thread.
// ---------------------------------------------------------------------------
template <int p, int q, int r>
__device__ __forceinline__ void jrot(float S[3][3], float V[3][3]) {
    float spq = S[p][q];
    if (fabsf(spq) > 1e-30f) {
        float tau = (S[q][q] - S[p][p]) / (2.0f * spq);
        float t   = copysignf(1.0f, tau) / (fabsf(tau) + sqrtf(1.0f + tau * tau));
        float c   = rsqrtf(1.0f + t * t);
        float sn  = t * c;
        float spp = S[p][p], sqq = S[q][q];
        S[p][p] = spp - t * spq;
        S[q][q] = sqq + t * spq;
        S[p][q] = 0.0f; S[q][p] = 0.0f;
        float srp = S[r][p], srq = S[r][q];
        S[r][p] = c * srp - sn * srq; S[p][r] = S[r][p];
        S[r][q] = sn * srp + c * srq; S[q][r] = S[r][q];
#pragma unroll
        for (int i = 0; i < 3; i++) {
            float vip = V[i][p], viq = V[i][q];
            V[i][p] = c * vip - sn * viq;
            V[i][q] = sn * vip + c * viq;
        }
    }
}

__device__ __forceinline__ void svd_project_write(const float* stash, float4* o) {
    float a[3][3] = {{stash[0], stash[1], stash[2]},
                     {stash[3], stash[4], stash[5]},
                     {stash[6], stash[7], stash[8]}};
    float inv = __fdividef(1.0f, stash[12]);
    float t0 = stash[9] * inv, t1 = stash[10] * inv, t2 = stash[11] * inv;

    float S[3][3];
#pragma unroll
    for (int c = 0; c < 3; c++)
#pragma unroll
        for (int d = c; d < 3; d++) {
            float v = a[0][c] * a[0][d] + a[1][c] * a[1][d] + a[2][c] * a[2][d];
            S[c][d] = v; S[d][c] = v;
        }

    float V[3][3] = {{1, 0, 0}, {0, 1, 0}, {0, 0, 1}};
#pragma unroll
    for (int sweep = 0; sweep < 5; sweep++) {
        jrot<0, 1, 2>(S, V);
        jrot<0, 2, 1>(S, V);
        jrot<1, 2, 0>(S, V);
    }

    float l0 = S[0][0], l1 = S[1][1], l2 = S[2][2];
    float v0x = V[0][0], v0y = V[1][0], v0z = V[2][0];
    float v1x = V[0][1], v1y = V[1][1], v1z = V[2][1];
    float v2x = V[0][2], v2y = V[1][2], v2z = V[2][2];

#define CSWAP(la, lb, ax, ay, az, bx, by, bz)                                  \
    if (la < lb) {                                                             \
        float tmp;                                                             \
        tmp = la; la = lb; lb = tmp;                                           \
        tmp = ax; ax = bx; bx = tmp;                                           \
        tmp = ay; ay = by; by = tmp;                                           \
        tmp = az; az = bz; bz = tmp;                                           \
    }
    CSWAP(l0, l1, v0x, v0y, v0z, v1x, v1y, v1z)
    CSWAP(l0, l2, v0x, v0y, v0z, v2x, v2y, v2z)
    CSWAP(l1, l2, v1x, v1y, v1z, v2x, v2y, v2z)
#undef CSWAP

    float cx = v1y * v2z - v1z * v2y;
    float cy = v1z * v2x - v1x * v2z;
    float cz = v1x * v2y - v1y * v2x;
    float det = v0x * cx + v0y * cy + v0z * cz;
    if (det < 0.0f) { v2x = -v2x; v2y = -v2y; v2z = -v2z; }

    float u0x = a[0][0] * v0x + a[0][1] * v0y + a[0][2] * v0z;
    float u0y = a[1][0] * v0x + a[1][1] * v0y + a[1][2] * v0z;
    float u0z = a[2][0] * v0x + a[2][1] * v0y + a[2][2] * v0z;
    float inv0 = rsqrtf(u0x * u0x + u0y * u0y + u0z * u0z + 1e-30f);
    u0x *= inv0; u0y *= inv0; u0z *= inv0;

    float u1x = a[0][0] * v1x + a[0][1] * v1y + a[0][2] * v1z;
    float u1y = a[1][0] * v1x + a[1][1] * v1y + a[1][2] * v1z;
    float u1z = a[2][0] * v1x + a[2][1] * v1y + a[2][2] * v1z;
    float dp = u0x * u1x + u0y * u1y + u0z * u1z;
    u1x -= dp * u0x; u1y -= dp * u0y; u1z -= dp * u0z;
    float inv1 = rsqrtf(u1x * u1x + u1y * u1y + u1z * u1z + 1e-30f);
    u1x *= inv1; u1y *= inv1; u1z *= inv1;

    float u2x = u0y * u1z - u0z * u1y;
    float u2y = u0z * u1x - u0x * u1z;
    float u2z = u0x * u1y - u0y * u1x;

    float R00 = u0x * v0x + u1x * v1x + u2x * v2x;
    float R01 = u0x * v0y + u1x * v1y + u2x * v2y;
    float R02 = u0x * v0z + u1x * v1z + u2x * v2z;
    float R10 = u0y * v0x + u1y * v1x + u2y * v2x;
    float R11 = u0y * v0y + u1y * v1y + u2y * v2y;
    float R12 = u0y * v0z + u1y * v1z + u2y * v2z;
    float R20 = u0z * v0x + u1z * v1x + u2z * v2x;
    float R21 = u0z * v0y + u1z * v1y + u2z * v2y;
    float R22 = u0z * v0z + u1z * v1z + u2z * v2z;

    o[0] = make_float4(R00, R01, R02, R10);
    o[1] = make_float4(R11, R12, R20, R21);
    o[2] = make_float4(R22, t0, t1, t2);
}

// ---------------------------------------------------------------------------
// Kernel 2 (compose + average + SVD) — byte-identical round-13 structure,
// with __ldcs (evict-first) on ALL stream-once loads (pair tiles, topo, conf)
// so L1 stays dedicated to the randomly-gathered frame table (256KB/batch vs
// 228KB L1 -> high hit rate once streams stop evicting it).
// ---------------------------------------------------------------------------
__global__ __launch_bounds__(CTHREADS) void compose_svd_kernel(
    const float* __restrict__ pair_rot,
    const float* __restrict__ pair_trans,
    const float* __restrict__ conf,
    const int*   __restrict__ topo,
    float*       __restrict__ out) {

    extern __shared__ float sm[];
    int tid  = threadIdx.x;
    int warp = tid >> 5;
    int lane = tid & 31;
    int g    = lane >> 3;
    int s    = lane & 7;

    int chunk = blockIdx.x + 148 * warp;   // balanced: every SM ~13-14 chunks
    if (chunk >= NCHUNK) return;           // uniform per warp; no __syncthreads

    int b = chunk >> 7;                    // 128 chunks per batch
    const float4* tab4 = (const float4*)g_frames + (size_t)(b << 12) * 4;

    float* rotbuf = sm + warp * WSM;
    float* trnbuf = rotbuf + 4 * TSR;
    float4* rb4 = (float4*)rotbuf;         // tile stride 74 float4
    float4* tb4 = (float4*)trnbuf;         // tile stride 26 float4

    const float4* pr4 = (const float4*)pair_rot;
    const float4* pt4 = (const float4*)pair_trans;

    size_t chunkbn = (size_t)chunk * 32;
    float stash[13];

    // --- prologue: topo + conf for iteration 0 (stream-once: evict-first) ---
    int   jj[4];
    float wgt[4];
    {
        const int*   tpb = topo + (chunkbn + g) * K;
        const float* cfb = conf + (chunkbn + g) * K;
#pragma unroll
        for (int i = 0; i < 4; i++) {
            jj[i]  = __ldcs(tpb + s + 8 * i);
            wgt[i] = __ldcs(cfb + s + 8 * i);
        }
    }

    for (int it = 0; it < 8; it++) {
        size_t bn0 = chunkbn + it * 4;

        // --- random frame gathers FIRST (default caching: L1-resident) ---
        float4 F[4][3];
#pragma unroll
        for (int i = 0; i < 4; i++) {
            const float4* Fp = tab4 + (size_t)jj[i] * 4;
            F[i][0] = Fp[0]; F[i][1] = Fp[1]; F[i][2] = Fp[2];
        }

        // --- stage pair tiles (stream-once loads: evict-first) ---
#pragma unroll
        for (int q = 0; q < 9; q++) {
            int f = q * 32 + lane;             // 0..287
            int t = f / 72, w = f - t * 72;
            rb4[t * 74 + w] = __ldcs(pr4 + bn0 * 72 + f);
        }
#pragma unroll
        for (int q = 0; q < 3; q++) {
            int f = q * 32 + lane;             // 0..95
            int t = f / 24, w = f - t * 24;
            tb4[t * 26 + w] = __ldcs(pt4 + bn0 * 24 + f);
        }

        // --- prefetch NEXT iteration's topo + conf (evict-first) ---
        int   jjn[4];
        float wgtn[4];
        if (it < 7) {
            const int*   tpbn = topo + (bn0 + 4 + g) * K;
            const float* cfbn = conf + (bn0 + 4 + g) * K;
#pragma unroll
            for (int i = 0; i < 4; i++) {
                jjn[i]  = __ldcs(tpbn + s + 8 * i);
                wgtn[i] = __ldcs(cfbn + s + 8 * i);
            }
        }
        __syncwarp();

        float acc[13];
#pragma unroll
        for (int v = 0; v < 13; v++) acc[v] = 0.0f;

#pragma unroll
        for (int i = 0; i < 4; i++) {
            int k = s + 8 * i;
            const float* P = rotbuf + g * TSR + k * 9;   // conflict-free LDS
            const float* Q = trnbuf + g * TST + k * 3;

            float w = wgt[i];
            float R0x = F[i][0].x, R0y = F[i][0].y, R0z = F[i][0].z;
            float R1x = F[i][0].w, R1y = F[i][1].x, R1z = F[i][1].y;
            float R2x = F[i][1].z, R2y = F[i][1].w, R2z = F[i][2].x;
            float tx  = F[i][2].y, ty  = F[i][2].z, tz  = F[i][2].w;

#pragma unroll
            for (int c = 0; c < 3; c++) {
                float p0 = P[c], p1 = P[3 + c], p2 = P[6 + c];
                acc[0 + c] += w * (R0x * p0 + R0y * p1 + R0z * p2);
                acc[3 + c] += w * (R1x * p0 + R1y * p1 + R1z * p2);
                acc[6 + c] += w * (R2x * p0 + R2y * p1 + R2z * p2);
            }
            float q0 = Q[0], q1 = Q[1], q2 = Q[2];
            acc[9]  += w * (R0x * q0 + R0y * q1 + R0z * q2 + tx);
            acc[10] += w * (R1x * q0 + R1y * q1 + R1z * q2 + ty);
            acc[11] += w * (R2x * q0 + R2y * q1 + R2z * q2 + tz);
            acc[12] += w;
        }
        __syncwarp();   // staging buffer reused next iteration

        // --- butterfly reduce within 8-lane groups ---
#pragma unroll
        for (int v = 0; v < 13; v++) {
            acc[v] += __shfl_xor_sync(0xffffffffu, acc[v], 4);
            acc[v] += __shfl_xor_sync(0xffffffffu, acc[v], 2);
            acc[v] += __shfl_xor_sync(0xffffffffu, acc[v], 1);
        }

        // --- stash: lane L = it*4 + g' collects group g' of iteration it ---
        int src = (lane & 3) * 8;
#pragma unroll
        for (int v = 0; v < 13; v++) {
            float tmp = __shfl_sync(0xffffffffu, acc[v], src);
            if ((lane >> 2) == it) stash[v] = tmp;
        }

        // --- rotate prefetched registers ---
        if (it < 7) {
#pragma unroll
            for (int i = 0; i < 4; i++) {
                jj[i]  = jjn[i];
                wgt[i] = wgtn[i];
            }
        }
    }

    // --- epilogue: 32 fully-parallel SVDs, one bn per lane ---
    float4* o = (float4*)out + (chunkbn + lane) * 3;
    svd_project_write(stash, o);
}

// ---------------------------------------------------------------------------
extern "C" void kernel_launch(void* const* d_in, const int* in_sizes, int n_in,
                              void* d_out, int out_size) {
    const float* frames_rot   = (const float*)d_in[0];
    const float* frames_trans = (const float*)d_in[1];
    const float* pair_rot     = (const float*)d_in[2];
    const float* pair_trans   = (const float*)d_in[3];
    const float* confidences  = (const float*)d_in[4];
    const int*   topology     = (const int*)d_in[5];
    float*       out          = (float*)d_out;

    cudaFuncSetAttribute(compose_svd_kernel,
                         cudaFuncAttributeMaxDynamicSharedMemorySize, CSMEM);

    repack_frames_kernel<<<BN / 256, 256>>>(frames_rot, frames_trans);
    compose_svd_kernel<<<148, CTHREADS, CSMEM>>>(pair_rot, pair_trans,
                                                 confidences, topology, out);
}